// round 13
// baseline (speedup 1.0000x reference)
#include <cuda_runtime.h>
#include <cuda_fp16.h>
#include <cstdint>
#include <math.h>

#define BATCH   2
#define SEQL    1024
#define DMODEL  768
#define DINNER  1536
#define DSTATE  16
#define DTRANK  48
#define MTOT    (BATCH*SEQL)
#define TOTOUT  52272
#define OFF_U   DINNER
#define OFF_DTH (2*DINNER)
#define OFF_B   (2*DINNER + DTRANK)
#define OFF_C   (OFF_B + DINNER*DSTATE)

/* ------------------------------ scratch ------------------------------------ */
__device__ __align__(16) __half g_hP [(size_t)MTOT * TOTOUT];
__device__ float g_dt [MTOT * DINNER];
__device__ float g_uc [MTOT * DINNER];
__device__ float g_y  [MTOT * DINNER];
__device__ float g_res[MTOT * DINNER];
__device__ __align__(16) __half g_hXn [MTOT * DMODEL];
__device__ __align__(16) __half g_hX  [MTOT * DMODEL];
__device__ __align__(16) __half g_hG  [MTOT * DINNER];
__device__ __align__(16) __half g_hWin [(size_t)TOTOUT * DMODEL];
__device__ __align__(16) __half g_hWres[DINNER * DMODEL];
__device__ __align__(16) __half g_hWout[DMODEL * DINNER];

/* ------------------------------- helpers ----------------------------------- */
__device__ __forceinline__ float block_sum256(float v, float* sm) {
    int tid = threadIdx.x;
    #pragma unroll
    for (int o = 16; o; o >>= 1) v += __shfl_down_sync(0xffffffffu, v, o);
    if ((tid & 31) == 0) sm[tid >> 5] = v;
    __syncthreads();
    if (tid < 32) {
        float r = (tid < 8) ? sm[tid] : 0.f;
        #pragma unroll
        for (int o = 4; o; o >>= 1) r += __shfl_down_sync(0xffffffffu, r, o);
        if (tid == 0) sm[0] = r;
    }
    __syncthreads();
    float r = sm[0];
    __syncthreads();
    return r;
}

/* 4 independent float4 loads per iteration for MLP */
__global__ void h_cvt(const float* __restrict__ src, __half* __restrict__ dst, int n4) {
    int i = (blockIdx.x * blockDim.x + threadIdx.x) * 4;
    int st = gridDim.x * blockDim.x * 4;
    for (; i < n4; i += st) {
        float4 v0 = ((const float4*)src)[i];
        float4 v1 = ((const float4*)src)[i + 1];
        float4 v2 = ((const float4*)src)[i + 2];
        float4 v3 = ((const float4*)src)[i + 3];
        ((__half2*)dst)[2*i+0] = __floats2half2_rn(v0.x, v0.y);
        ((__half2*)dst)[2*i+1] = __floats2half2_rn(v0.z, v0.w);
        ((__half2*)dst)[2*i+2] = __floats2half2_rn(v1.x, v1.y);
        ((__half2*)dst)[2*i+3] = __floats2half2_rn(v1.z, v1.w);
        ((__half2*)dst)[2*i+4] = __floats2half2_rn(v2.x, v2.y);
        ((__half2*)dst)[2*i+5] = __floats2half2_rn(v2.z, v2.w);
        ((__half2*)dst)[2*i+6] = __floats2half2_rn(v3.x, v3.y);
        ((__half2*)dst)[2*i+7] = __floats2half2_rn(v3.z, v3.w);
    }
}

__global__ void ln_kernel(const float* __restrict__ x, const float* __restrict__ w,
                          const float* __restrict__ bb, __half* __restrict__ out) {
    __shared__ float sm[8];
    int m = blockIdx.x, tid = threadIdx.x;
    const float* row = x + (size_t)m * DMODEL;
    float v0 = row[tid], v1 = row[tid + 256], v2 = row[tid + 512];
    float s = block_sum256(v0 + v1 + v2, sm);
    float mu = s * (1.f / (float)DMODEL);
    float d0 = v0 - mu, d1 = v1 - mu, d2 = v2 - mu;
    float q = block_sum256(d0 * d0 + d1 * d1 + d2 * d2, sm);
    float inv = rsqrtf(q * (1.f / (float)DMODEL) + 1e-5f);
    __half* o = out + (size_t)m * DMODEL;
    o[tid]       = __float2half_rn(d0 * inv * w[tid]       + bb[tid]);
    o[tid + 256] = __float2half_rn(d1 * inv * w[tid + 256] + bb[tid + 256]);
    o[tid + 512] = __float2half_rn(d2 * inv * w[tid + 512] + bb[tid + 512]);
}

/* ============== fp16 tensor-core GEMM: C[M,N]=A[M,K]*B[N,K]^T ===============
   tile 128x128, BK=64, 3-stage cp.async, one sync/step, 2 CTAs/SM. */
template<int HOUT>
__global__ void __launch_bounds__(256, 2)
gemm_h(const __half* __restrict__ A, const __half* __restrict__ B,
       void* __restrict__ Cv, int N, int K, int lda, int ldb, int ldc)
{
    extern __shared__ char smem_raw[];
    const unsigned sraw  = (unsigned)__cvta_generic_to_shared(smem_raw);
    const unsigned sbase = (sraw + 1023u) & ~1023u;
    constexpr unsigned STG = 32768u;

    const int tid = threadIdx.x, lane = tid & 31, warp = tid >> 5;
    const int wm = (warp & 1) * 64, wn = (warp >> 1) * 32;
    const int bm0 = blockIdx.y * 128, bn0 = blockIdx.x * 128;

    float acc[4][4][4];
    #pragma unroll
    for (int i = 0; i < 4; i++)
        #pragma unroll
        for (int j = 0; j < 4; j++)
            #pragma unroll
            for (int k = 0; k < 4; k++) acc[i][j][k] = 0.f;

    const int arow  = lane & 15;
    const int abyte = (lane & 16) ? 16 : 0;
    const int brow  = (lane & 7) + ((lane & 16) ? 8 : 0);
    const int bbyte = (lane & 8) ? 16 : 0;

    auto load_stage = [&](int t) {
        unsigned stg = sbase + (unsigned)(t % 3) * STG;
        int k0 = t * 64;
        #pragma unroll
        for (int i = 0; i < 4; i++) {
            int si = tid * 4 + i;
            int r = si >> 3, sg = si & 7;
            unsigned off = (unsigned)(r * 128 + sg * 16);
            unsigned sw = off ^ ((off >> 3) & 0x70u);
            const __half* g = A + (size_t)(bm0 + r) * lda + k0 + sg * 8;
            asm volatile("cp.async.cg.shared.global [%0], [%1], 16;"
                         :: "r"(stg + sw), "l"(g));
        }
        #pragma unroll
        for (int i = 0; i < 4; i++) {
            int si = tid * 4 + i;
            int r = si >> 3, sg = si & 7;
            int n = bn0 + r;
            unsigned off = (unsigned)(r * 128 + sg * 16);
            unsigned sw = off ^ ((off >> 3) & 0x70u);
            const __half* g = B + (size_t)(n < N ? n : N - 1) * ldb + k0 + sg * 8;
            int bytes = (n < N) ? 16 : 0;
            asm volatile("cp.async.cg.shared.global [%0], [%1], 16, %2;"
                         :: "r"(stg + 16384u + sw), "l"(g), "r"(bytes));
        }
    };

    auto compute_stage = [&](int s) {
        unsigned aB = sbase + (unsigned)(s % 3) * STG;
        unsigned bB = aB + 16384u;
        #pragma unroll
        for (int ks = 0; ks < 4; ks++) {
            unsigned a[4][4], b[2][4];
            #pragma unroll
            for (int mi = 0; mi < 4; mi++) {
                unsigned off = (unsigned)((wm + mi * 16 + arow) * 128 + ks * 32 + abyte);
                unsigned ad = aB + (off ^ ((off >> 3) & 0x70u));
                asm volatile("ldmatrix.sync.aligned.m8n8.x4.shared.b16 {%0,%1,%2,%3}, [%4];"
                             : "=r"(a[mi][0]), "=r"(a[mi][1]), "=r"(a[mi][2]), "=r"(a[mi][3])
                             : "r"(ad));
            }
            #pragma unroll
            for (int bg = 0; bg < 2; bg++) {
                unsigned off = (unsigned)((wn + bg * 16 + brow) * 128 + ks * 32 + bbyte);
                unsigned ad = bB + (off ^ ((off >> 3) & 0x70u));
                asm volatile("ldmatrix.sync.aligned.m8n8.x4.shared.b16 {%0,%1,%2,%3}, [%4];"
                             : "=r"(b[bg][0]), "=r"(b[bg][1]), "=r"(b[bg][2]), "=r"(b[bg][3])
                             : "r"(ad));
            }
            #pragma unroll
            for (int mi = 0; mi < 4; mi++)
                #pragma unroll
                for (int nj = 0; nj < 4; nj++) {
                    unsigned b0 = b[nj >> 1][(nj & 1) * 2];
                    unsigned b1 = b[nj >> 1][(nj & 1) * 2 + 1];
                    asm volatile(
                        "mma.sync.aligned.m16n8k16.row.col.f32.f16.f16.f32 "
                        "{%0,%1,%2,%3}, {%4,%5,%6,%7}, {%8,%9}, {%0,%1,%2,%3};"
                        : "+f"(acc[mi][nj][0]), "+f"(acc[mi][nj][1]),
                          "+f"(acc[mi][nj][2]), "+f"(acc[mi][nj][3])
                        : "r"(a[mi][0]), "r"(a[mi][1]), "r"(a[mi][2]), "r"(a[mi][3]),
                          "r"(b0), "r"(b1));
                }
        }
    };

    const int nst = K >> 6;
    load_stage(0); asm volatile("cp.async.commit_group;");
    load_stage(1); asm volatile("cp.async.commit_group;");
    for (int s = 0; s < nst; s++) {
        if (s + 1 < nst) asm volatile("cp.async.wait_group 1;");
        else             asm volatile("cp.async.wait_group 0;");
        __syncthreads();
        if (s + 2 < nst) { load_stage(s + 2); asm volatile("cp.async.commit_group;"); }
        compute_stage(s);
    }

    #pragma unroll
    for (int mi = 0; mi < 4; mi++)
        #pragma unroll
        for (int nj = 0; nj < 4; nj++) {
            int row = bm0 + wm + mi * 16 + (lane >> 2);
            int col = bn0 + wn + nj * 8 + (lane & 3) * 2;
            if (col < N) {
                if (HOUT) {
                    __half* Ch = (__half*)Cv;
                    *(__half2*)(Ch + (size_t)row * ldc + col) =
                        __floats2half2_rn(acc[mi][nj][0], acc[mi][nj][1]);
                    *(__half2*)(Ch + (size_t)(row + 8) * ldc + col) =
                        __floats2half2_rn(acc[mi][nj][2], acc[mi][nj][3]);
                } else {
                    float* C = (float*)Cv;
                    *(float2*)(C + (size_t)row * ldc + col) =
                        make_float2(acc[mi][nj][0], acc[mi][nj][1]);
                    *(float2*)(C + (size_t)(row + 8) * ldc + col) =
                        make_float2(acc[mi][nj][2], acc[mi][nj][3]);
                }
            }
        }
}

/* -------- fused dt projection + softplus/clip + causal depthwise conv ------
   block = 16 rows; computes dt and uc directly from hp (no dtl round-trip). */
__global__ void dtprep_kernel(const __half* __restrict__ p, const float* __restrict__ Wdt,
                              const float* __restrict__ dt_bias,
                              const float* __restrict__ conv_w, const float* __restrict__ conv_b,
                              float* __restrict__ dt_out, float* __restrict__ uc_out)
{
    __shared__ float sA[16][48];
    int m0 = blockIdx.x * 16, tid = threadIdx.x;
    int l0 = m0 & (SEQL - 1);
    for (int i = tid; i < 16 * 48; i += 256)
        sA[i / 48][i % 48] = __half2float(p[(size_t)(m0 + i / 48) * TOTOUT + OFF_DTH + (i % 48)]);
    __syncthreads();
    for (int d = tid; d < DINNER; d += 256) {
        float w[48];
        #pragma unroll
        for (int k = 0; k < 48; k++) w[k] = Wdt[d * 48 + k];
        float bias = dt_bias[d];
        float4 cw = *(const float4*)(conv_w + d * 4);
        float cb = conv_b[d];
        float uu[19];
        #pragma unroll
        for (int j = 0; j < 19; j++) {
            bool valid = (l0 + j - 3) >= 0;
            uu[j] = valid ? __half2float(p[(size_t)(m0 + j - 3) * TOTOUT + OFF_U + d]) : 0.f;
        }
        #pragma unroll
        for (int r = 0; r < 16; r++) {
            float acc = bias;
            #pragma unroll
            for (int k = 0; k < 48; k++) acc = fmaf(sA[r][k], w[k], acc);
            float sp = (acc > 20.f) ? acc : log1pf(expf(acc));
            dt_out[(size_t)(m0 + r) * DINNER + d] = fminf(fmaxf(sp, 1e-4f), 1.0f);
            uc_out[(size_t)(m0 + r) * DINNER + d] =
                cb + cw.x*uu[r] + cw.y*uu[r+1] + cw.z*uu[r+2] + cw.w*uu[r+3];
        }
    }
}

/* ------ selective scan: 16 lanes/chain (1 state each), 192 x 256 thr -------
   dt/uc loads are same-address within the 16-lane group -> coalesced to one
   transaction; B/C are 2-byte fp16 loads, contiguous across lanes. */
__global__ void scan_kernel(const __half* __restrict__ p, const float* __restrict__ dt,
                            const float* __restrict__ uc, const float* __restrict__ A_log,
                            const float* __restrict__ Dskip, float* __restrict__ y)
{
    int t = blockIdx.x * blockDim.x + threadIdx.x;  /* 49152 = 3072 chains * 16 */
    int chain = t >> 4, n = t & 15;
    int b = chain / DINNER, d = chain - b * DINNER;
    float a = -__expf(A_log[d * DSTATE + n]);
    float dsk = Dskip[d];
    size_t basep = (size_t)b * SEQL * TOTOUT;
    const __half* pB = p + basep + OFF_B + d * DSTATE + n;
    const __half* pC = p + basep + OFF_C + d * DSTATE + n;
    size_t base2 = (size_t)b * SEQL * DINNER + d;
    const float* pdt = dt + base2;
    const float* puc = uc + base2;
    float* py = y + base2;

    __half Bb[4], Cb[4]; float dtb[4], ucb[4];
    #pragma unroll
    for (int s = 0; s < 4; s++) {
        Bb[s]  = pB[(size_t)s * TOTOUT];
        Cb[s]  = pC[(size_t)s * TOTOUT];
        dtb[s] = pdt[(size_t)s * DINNER];
        ucb[s] = puc[(size_t)s * DINNER];
    }
    float h = 0.f;
    #pragma unroll 4
    for (int l = 0; l < SEQL; l++) {
        int sl = l & 3;
        float dtv = dtb[sl], ucv = ucb[sl];
        float Bv = __half2float(Bb[sl]), Cv = __half2float(Cb[sl]);
        int lp = l + 4;
        if (lp < SEQL) {
            Bb[sl]  = pB[(size_t)lp * TOTOUT];
            Cb[sl]  = pC[(size_t)lp * TOTOUT];
            dtb[sl] = pdt[(size_t)lp * DINNER];
            ucb[sl] = puc[(size_t)lp * DINNER];
        }
        h = fmaf(h, __expf(dtv * a), dtv * ucv * Bv);
        float part = Cv * h;
        part += __shfl_xor_sync(0xffffffffu, part, 8, 16);
        part += __shfl_xor_sync(0xffffffffu, part, 4, 16);
        part += __shfl_xor_sync(0xffffffffu, part, 2, 16);
        part += __shfl_xor_sync(0xffffffffu, part, 1, 16);
        if (n == 0) py[(size_t)l * DINNER] = fmaf(ucv, dsk, part);
    }
}

__global__ void gate_kernel(const float* __restrict__ y, const __half* __restrict__ p,
                            const float* __restrict__ norm_w, const float* __restrict__ res,
                            __half* __restrict__ g)
{
    __shared__ float sm[8];
    int m = blockIdx.x, tid = threadIdx.x;
    float gv[6], ss = 0.f;
    #pragma unroll
    for (int i = 0; i < 6; i++) {
        int d = tid + i * 256;
        float z = __half2float(p[(size_t)m * TOTOUT + d]);
        float yv = y[(size_t)m * DINNER + d];
        gv[i] = yv * z / (1.f + __expf(-z));
        ss += gv[i] * gv[i];
    }
    float tot = block_sum256(ss, sm);
    float r = rsqrtf(tot * (1.f / (float)DINNER) + 1e-6f);
    #pragma unroll
    for (int i = 0; i < 6; i++) {
        int d = tid + i * 256;
        g[(size_t)m * DINNER + d] =
            __float2half_rn(gv[i] * r * norm_w[d] + res[(size_t)m * DINNER + d]);
    }
}

/* --------------------------------- launch ---------------------------------- */
extern "C" void kernel_launch(void* const* d_in, const int* in_sizes, int n_in,
                              void* d_out, int out_size)
{
    (void)in_sizes; (void)n_in; (void)out_size;
    const float* x       = (const float*)d_in[0];
    const float* ln_w    = (const float*)d_in[1];
    const float* ln_b    = (const float*)d_in[2];
    const float* W_in    = (const float*)d_in[3];
    const float* W_dt    = (const float*)d_in[4];
    const float* conv_w  = (const float*)d_in[5];
    const float* conv_b  = (const float*)d_in[6];
    const float* A_log   = (const float*)d_in[7];
    const float* Dskip   = (const float*)d_in[8];
    const float* dt_bias = (const float*)d_in[9];
    const float* norm_w  = (const float*)d_in[10];
    const float* W_res   = (const float*)d_in[11];
    const float* W_out   = (const float*)d_in[12];
    float* out = (float*)d_out;

    float *dtc, *ucb, *yb, *resb;
    __half *hp, *hxn, *hx, *hg, *hwin, *hwres, *hwout;
    cudaGetSymbolAddress((void**)&hp,    g_hP);
    cudaGetSymbolAddress((void**)&dtc,   g_dt);
    cudaGetSymbolAddress((void**)&ucb,   g_uc);
    cudaGetSymbolAddress((void**)&yb,    g_y);
    cudaGetSymbolAddress((void**)&resb,  g_res);
    cudaGetSymbolAddress((void**)&hxn,   g_hXn);
    cudaGetSymbolAddress((void**)&hx,    g_hX);
    cudaGetSymbolAddress((void**)&hg,    g_hG);
    cudaGetSymbolAddress((void**)&hwin,  g_hWin);
    cudaGetSymbolAddress((void**)&hwres, g_hWres);
    cudaGetSymbolAddress((void**)&hwout, g_hWout);

    const int SMEMSZ = 3 * 32768 + 1024;
    cudaFuncSetAttribute(gemm_h<0>, cudaFuncAttributeMaxDynamicSharedMemorySize, SMEMSZ);
    cudaFuncSetAttribute(gemm_h<1>, cudaFuncAttributeMaxDynamicSharedMemorySize, SMEMSZ);

    /* fp16 conversions (4 float4 per thread-iter) */
    h_cvt<<<2452, 256>>>(W_in,  hwin,  (int)((size_t)TOTOUT * DMODEL / 4));
    h_cvt<<<288,  256>>>(W_res, hwres, DINNER * DMODEL / 4);
    h_cvt<<<288,  256>>>(W_out, hwout, DMODEL * DINNER / 4);
    h_cvt<<<384,  256>>>(x,     hx,    MTOT * DMODEL / 4);

    ln_kernel<<<MTOT, 256>>>(x, ln_w, ln_b, hxn);

    /* p = xn @ W_in^T : 2048 x 52272, K=768  (fp16 output) */
    gemm_h<1><<<dim3((TOTOUT + 127) / 128, MTOT / 128), 256, SMEMSZ>>>(
        hxn, hwin, hp, TOTOUT, DMODEL, DMODEL, DMODEL, TOTOUT);

    dtprep_kernel<<<MTOT / 16, 256>>>(hp, W_dt, dt_bias, conv_w, conv_b, dtc, ucb);
    scan_kernel<<<192, 256>>>(hp, dtc, ucb, A_log, Dskip, yb);

    /* res = x @ W_res^T : 2048 x 1536, K=768 */
    gemm_h<0><<<dim3(DINNER / 128, MTOT / 128), 256, SMEMSZ>>>(
        hx, hwres, resb, DINNER, DMODEL, DMODEL, DMODEL, DINNER);

    gate_kernel<<<MTOT, 256>>>(yb, hp, norm_w, resb, hg);

    /* out = g @ W_out^T : 2048 x 768, K=1536 */
    gemm_h<0><<<dim3(DMODEL / 128, MTOT / 128), 256, SMEMSZ>>>(
        hg, hwout, out, DMODEL, DINNER, DINNER, DINNER, DMODEL);
}

// round 14
// speedup vs baseline: 1.0880x; 1.0880x over previous
#include <cuda_runtime.h>
#include <cuda_fp16.h>
#include <cstdint>
#include <math.h>

#define BATCH   2
#define SEQL    1024
#define DMODEL  768
#define DINNER  1536
#define DSTATE  16
#define DTRANK  48
#define MTOT    (BATCH*SEQL)
#define TOTOUT  52272
#define OFF_U   DINNER
#define OFF_DTH (2*DINNER)
#define OFF_B   (2*DINNER + DTRANK)
#define OFF_C   (OFF_B + DINNER*DSTATE)

/* ------------------------------ scratch ------------------------------------ */
__device__ __align__(16) __half g_hP [(size_t)MTOT * TOTOUT];
__device__ float g_dt [MTOT * DINNER];
__device__ float g_uc [MTOT * DINNER];
__device__ float g_y  [MTOT * DINNER];
__device__ float g_res[MTOT * DINNER];
__device__ __align__(16) __half g_hXn [MTOT * DMODEL];
__device__ __align__(16) __half g_hX  [MTOT * DMODEL];
__device__ __align__(16) __half g_hG  [MTOT * DINNER];
__device__ __align__(16) __half g_hWin [(size_t)TOTOUT * DMODEL];
__device__ __align__(16) __half g_hWres[DINNER * DMODEL];
__device__ __align__(16) __half g_hWout[DMODEL * DINNER];

/* ------------------------------- helpers ----------------------------------- */
__device__ __forceinline__ float block_sum256(float v, float* sm) {
    int tid = threadIdx.x;
    #pragma unroll
    for (int o = 16; o; o >>= 1) v += __shfl_down_sync(0xffffffffu, v, o);
    if ((tid & 31) == 0) sm[tid >> 5] = v;
    __syncthreads();
    if (tid < 32) {
        float r = (tid < 8) ? sm[tid] : 0.f;
        #pragma unroll
        for (int o = 4; o; o >>= 1) r += __shfl_down_sync(0xffffffffu, r, o);
        if (tid == 0) sm[0] = r;
    }
    __syncthreads();
    float r = sm[0];
    __syncthreads();
    return r;
}

__global__ void h_cvt(const float* __restrict__ src, __half* __restrict__ dst, int n4) {
    int i = blockIdx.x * blockDim.x + threadIdx.x, st = gridDim.x * blockDim.x;
    for (; i < n4; i += st) {
        float4 v = ((const float4*)src)[i];
        ((__half2*)dst)[2 * i]     = __floats2half2_rn(v.x, v.y);
        ((__half2*)dst)[2 * i + 1] = __floats2half2_rn(v.z, v.w);
    }
}

/* layernorm -> hxn, plus raw x -> hx (saves a separate conversion pass) */
__global__ void ln_kernel(const float* __restrict__ x, const float* __restrict__ w,
                          const float* __restrict__ bb,
                          __half* __restrict__ out, __half* __restrict__ outx) {
    __shared__ float sm[8];
    int m = blockIdx.x, tid = threadIdx.x;
    const float* row = x + (size_t)m * DMODEL;
    float v0 = row[tid], v1 = row[tid + 256], v2 = row[tid + 512];
    float s = block_sum256(v0 + v1 + v2, sm);
    float mu = s * (1.f / (float)DMODEL);
    float d0 = v0 - mu, d1 = v1 - mu, d2 = v2 - mu;
    float q = block_sum256(d0 * d0 + d1 * d1 + d2 * d2, sm);
    float inv = rsqrtf(q * (1.f / (float)DMODEL) + 1e-5f);
    __half* o  = out  + (size_t)m * DMODEL;
    __half* ox = outx + (size_t)m * DMODEL;
    o[tid]       = __float2half_rn(d0 * inv * w[tid]       + bb[tid]);
    o[tid + 256] = __float2half_rn(d1 * inv * w[tid + 256] + bb[tid + 256]);
    o[tid + 512] = __float2half_rn(d2 * inv * w[tid + 512] + bb[tid + 512]);
    ox[tid]       = __float2half_rn(v0);
    ox[tid + 256] = __float2half_rn(v1);
    ox[tid + 512] = __float2half_rn(v2);
}

/* ============== fp16 tensor-core GEMM: C[M,N]=A[M,K]*B[N,K]^T ===============
   tile 128x128, BK=64, 3-stage cp.async, one sync/step, 2 CTAs/SM.
   grid: x = M tiles (fastest) -> one wave covers all M tiles of ~18 N tiles,
   so each B (weight) slice is loaded from DRAM once and reused 16x via L2. */
template<int HOUT>
__global__ void __launch_bounds__(256, 2)
gemm_h(const __half* __restrict__ A, const __half* __restrict__ B,
       void* __restrict__ Cv, int N, int K, int lda, int ldb, int ldc)
{
    extern __shared__ char smem_raw[];
    const unsigned sraw  = (unsigned)__cvta_generic_to_shared(smem_raw);
    const unsigned sbase = (sraw + 1023u) & ~1023u;
    constexpr unsigned STG = 32768u;

    const int tid = threadIdx.x, lane = tid & 31, warp = tid >> 5;
    const int wm = (warp & 1) * 64, wn = (warp >> 1) * 32;
    const int bm0 = blockIdx.x * 128, bn0 = blockIdx.y * 128;

    float acc[4][4][4];
    #pragma unroll
    for (int i = 0; i < 4; i++)
        #pragma unroll
        for (int j = 0; j < 4; j++)
            #pragma unroll
            for (int k = 0; k < 4; k++) acc[i][j][k] = 0.f;

    const int arow  = lane & 15;
    const int abyte = (lane & 16) ? 16 : 0;
    const int brow  = (lane & 7) + ((lane & 16) ? 8 : 0);
    const int bbyte = (lane & 8) ? 16 : 0;

    auto load_stage = [&](int t) {
        unsigned stg = sbase + (unsigned)(t % 3) * STG;
        int k0 = t * 64;
        #pragma unroll
        for (int i = 0; i < 4; i++) {          /* A: 128 rows x 128B */
            int si = tid * 4 + i;
            int r = si >> 3, sg = si & 7;
            unsigned off = (unsigned)(r * 128 + sg * 16);
            unsigned sw = off ^ ((off >> 3) & 0x70u);
            const __half* g = A + (size_t)(bm0 + r) * lda + k0 + sg * 8;
            asm volatile("cp.async.cg.shared.global [%0], [%1], 16;"
                         :: "r"(stg + sw), "l"(g));
        }
        #pragma unroll
        for (int i = 0; i < 4; i++) {          /* B: 128 rows x 128B */
            int si = tid * 4 + i;
            int r = si >> 3, sg = si & 7;
            int n = bn0 + r;
            unsigned off = (unsigned)(r * 128 + sg * 16);
            unsigned sw = off ^ ((off >> 3) & 0x70u);
            const __half* g = B + (size_t)(n < N ? n : N - 1) * ldb + k0 + sg * 8;
            int bytes = (n < N) ? 16 : 0;
            asm volatile("cp.async.cg.shared.global [%0], [%1], 16, %2;"
                         :: "r"(stg + 16384u + sw), "l"(g), "r"(bytes));
        }
    };

    auto compute_stage = [&](int s) {
        unsigned aB = sbase + (unsigned)(s % 3) * STG;
        unsigned bB = aB + 16384u;
        #pragma unroll
        for (int ks = 0; ks < 4; ks++) {
            unsigned a[4][4], b[2][4];
            #pragma unroll
            for (int mi = 0; mi < 4; mi++) {
                unsigned off = (unsigned)((wm + mi * 16 + arow) * 128 + ks * 32 + abyte);
                unsigned ad = aB + (off ^ ((off >> 3) & 0x70u));
                asm volatile("ldmatrix.sync.aligned.m8n8.x4.shared.b16 {%0,%1,%2,%3}, [%4];"
                             : "=r"(a[mi][0]), "=r"(a[mi][1]), "=r"(a[mi][2]), "=r"(a[mi][3])
                             : "r"(ad));
            }
            #pragma unroll
            for (int bg = 0; bg < 2; bg++) {
                unsigned off = (unsigned)((wn + bg * 16 + brow) * 128 + ks * 32 + bbyte);
                unsigned ad = bB + (off ^ ((off >> 3) & 0x70u));
                asm volatile("ldmatrix.sync.aligned.m8n8.x4.shared.b16 {%0,%1,%2,%3}, [%4];"
                             : "=r"(b[bg][0]), "=r"(b[bg][1]), "=r"(b[bg][2]), "=r"(b[bg][3])
                             : "r"(ad));
            }
            #pragma unroll
            for (int mi = 0; mi < 4; mi++)
                #pragma unroll
                for (int nj = 0; nj < 4; nj++) {
                    unsigned b0 = b[nj >> 1][(nj & 1) * 2];
                    unsigned b1 = b[nj >> 1][(nj & 1) * 2 + 1];
                    asm volatile(
                        "mma.sync.aligned.m16n8k16.row.col.f32.f16.f16.f32 "
                        "{%0,%1,%2,%3}, {%4,%5,%6,%7}, {%8,%9}, {%0,%1,%2,%3};"
                        : "+f"(acc[mi][nj][0]), "+f"(acc[mi][nj][1]),
                          "+f"(acc[mi][nj][2]), "+f"(acc[mi][nj][3])
                        : "r"(a[mi][0]), "r"(a[mi][1]), "r"(a[mi][2]), "r"(a[mi][3]),
                          "r"(b0), "r"(b1));
                }
        }
    };

    const int nst = K >> 6;
    load_stage(0); asm volatile("cp.async.commit_group;");
    load_stage(1); asm volatile("cp.async.commit_group;");
    for (int s = 0; s < nst; s++) {
        if (s + 1 < nst) asm volatile("cp.async.wait_group 1;");
        else             asm volatile("cp.async.wait_group 0;");
        __syncthreads();
        if (s + 2 < nst) { load_stage(s + 2); asm volatile("cp.async.commit_group;"); }
        compute_stage(s);
    }

    #pragma unroll
    for (int mi = 0; mi < 4; mi++)
        #pragma unroll
        for (int nj = 0; nj < 4; nj++) {
            int row = bm0 + wm + mi * 16 + (lane >> 2);
            int col = bn0 + wn + nj * 8 + (lane & 3) * 2;
            if (col < N) {
                if (HOUT) {
                    __half* Ch = (__half*)Cv;
                    *(__half2*)(Ch + (size_t)row * ldc + col) =
                        __floats2half2_rn(acc[mi][nj][0], acc[mi][nj][1]);
                    *(__half2*)(Ch + (size_t)(row + 8) * ldc + col) =
                        __floats2half2_rn(acc[mi][nj][2], acc[mi][nj][3]);
                } else {
                    float* C = (float*)Cv;
                    *(float2*)(C + (size_t)row * ldc + col) =
                        make_float2(acc[mi][nj][0], acc[mi][nj][1]);
                    *(float2*)(C + (size_t)(row + 8) * ldc + col) =
                        make_float2(acc[mi][nj][2], acc[mi][nj][3]);
                }
            }
        }
}

/* -------- fused dt projection + softplus/clip + causal depthwise conv ------ */
__global__ void dtprep_kernel(const __half* __restrict__ p, const float* __restrict__ Wdt,
                              const float* __restrict__ dt_bias,
                              const float* __restrict__ conv_w, const float* __restrict__ conv_b,
                              float* __restrict__ dt_out, float* __restrict__ uc_out)
{
    __shared__ float sA[16][48];
    int m0 = blockIdx.x * 16, tid = threadIdx.x;
    int l0 = m0 & (SEQL - 1);
    for (int i = tid; i < 16 * 48; i += 256)
        sA[i / 48][i % 48] = __half2float(p[(size_t)(m0 + i / 48) * TOTOUT + OFF_DTH + (i % 48)]);
    __syncthreads();
    for (int d = tid; d < DINNER; d += 256) {
        float w[48];
        #pragma unroll
        for (int k = 0; k < 48; k++) w[k] = Wdt[d * 48 + k];
        float bias = dt_bias[d];
        float4 cw = *(const float4*)(conv_w + d * 4);
        float cb = conv_b[d];
        float uu[19];
        #pragma unroll
        for (int j = 0; j < 19; j++) {
            bool valid = (l0 + j - 3) >= 0;
            uu[j] = valid ? __half2float(p[(size_t)(m0 + j - 3) * TOTOUT + OFF_U + d]) : 0.f;
        }
        #pragma unroll
        for (int r = 0; r < 16; r++) {
            float acc = bias;
            #pragma unroll
            for (int k = 0; k < 48; k++) acc = fmaf(sA[r][k], w[k], acc);
            float sp = (acc > 20.f) ? acc : log1pf(expf(acc));
            dt_out[(size_t)(m0 + r) * DINNER + d] = fminf(fmaxf(sp, 1e-4f), 1.0f);
            uc_out[(size_t)(m0 + r) * DINNER + d] =
                cb + cw.x*uu[r] + cw.y*uu[r+1] + cw.z*uu[r+2] + cw.w*uu[r+3];
        }
    }
}

/* ------- selective scan: 4 lanes/chain, depth-8 prefetch, 192 x 64thr ------ */
__global__ void scan_kernel(const __half* __restrict__ p, const float* __restrict__ dt,
                            const float* __restrict__ uc, const float* __restrict__ A_log,
                            const float* __restrict__ Dskip, float* __restrict__ y)
{
    int t = blockIdx.x * blockDim.x + threadIdx.x;   /* 12288 = 3072 chains * 4 */
    int chain = t >> 2, part = t & 3;
    int b = chain / DINNER, d = chain - b * DINNER, n0 = part * 4;

    float a0 = -__expf(A_log[d*DSTATE+n0+0]), a1 = -__expf(A_log[d*DSTATE+n0+1]);
    float a2 = -__expf(A_log[d*DSTATE+n0+2]), a3 = -__expf(A_log[d*DSTATE+n0+3]);
    float dsk = Dskip[d];
    size_t basep = (size_t)b * SEQL * TOTOUT;
    const __half* pB = p + basep + OFF_B + d * DSTATE + n0;
    const __half* pC = p + basep + OFF_C + d * DSTATE + n0;
    size_t base2 = (size_t)b * SEQL * DINNER + d;
    const float* pdt = dt + base2;
    const float* puc = uc + base2;
    float* py = y + base2;

    uint2 Bb[8], Cb[8]; float dtb[8], ucb[8];
    #pragma unroll
    for (int s = 0; s < 8; s++) {
        Bb[s]  = *(const uint2*)(pB + (size_t)s * TOTOUT);
        Cb[s]  = *(const uint2*)(pC + (size_t)s * TOTOUT);
        dtb[s] = pdt[(size_t)s * DINNER];
        ucb[s] = puc[(size_t)s * DINNER];
    }
    float h0 = 0.f, h1 = 0.f, h2 = 0.f, h3 = 0.f;
    #pragma unroll 8
    for (int l = 0; l < SEQL; l++) {
        int sl = l & 7;
        float dtv = dtb[sl], ucv = ucb[sl];
        uint2 Bu = Bb[sl], Cu = Cb[sl];
        int lp = l + 8;
        if (lp < SEQL) {
            Bb[sl]  = *(const uint2*)(pB + (size_t)lp * TOTOUT);
            Cb[sl]  = *(const uint2*)(pC + (size_t)lp * TOTOUT);
            dtb[sl] = pdt[(size_t)lp * DINNER];
            ucb[sl] = puc[(size_t)lp * DINNER];
        }
        float2 B01 = __half22float2(*(__half2*)&Bu.x);
        float2 B23 = __half22float2(*(__half2*)&Bu.y);
        float2 C01 = __half22float2(*(__half2*)&Cu.x);
        float2 C23 = __half22float2(*(__half2*)&Cu.y);
        float dtu = dtv * ucv;
        h0 = fmaf(h0, __expf(dtv*a0), dtu*B01.x);
        h1 = fmaf(h1, __expf(dtv*a1), dtu*B01.y);
        h2 = fmaf(h2, __expf(dtv*a2), dtu*B23.x);
        h3 = fmaf(h3, __expf(dtv*a3), dtu*B23.y);
        float acc = C01.x*h0 + C01.y*h1 + C23.x*h2 + C23.y*h3;
        acc += __shfl_down_sync(0xffffffffu, acc, 2, 4);
        acc += __shfl_down_sync(0xffffffffu, acc, 1, 4);
        if (part == 0) py[(size_t)l * DINNER] = fmaf(ucv, dsk, acc);
    }
}

__global__ void gate_kernel(const float* __restrict__ y, const __half* __restrict__ p,
                            const float* __restrict__ norm_w, const float* __restrict__ res,
                            __half* __restrict__ g)
{
    __shared__ float sm[8];
    int m = blockIdx.x, tid = threadIdx.x;
    float gv[6], ss = 0.f;
    #pragma unroll
    for (int i = 0; i < 6; i++) {
        int d = tid + i * 256;
        float z = __half2float(p[(size_t)m * TOTOUT + d]);
        float yv = y[(size_t)m * DINNER + d];
        gv[i] = yv * z / (1.f + __expf(-z));
        ss += gv[i] * gv[i];
    }
    float tot = block_sum256(ss, sm);
    float r = rsqrtf(tot * (1.f / (float)DINNER) + 1e-6f);
    #pragma unroll
    for (int i = 0; i < 6; i++) {
        int d = tid + i * 256;
        g[(size_t)m * DINNER + d] =
            __float2half_rn(gv[i] * r * norm_w[d] + res[(size_t)m * DINNER + d]);
    }
}

/* --------------------------------- launch ---------------------------------- */
extern "C" void kernel_launch(void* const* d_in, const int* in_sizes, int n_in,
                              void* d_out, int out_size)
{
    (void)in_sizes; (void)n_in; (void)out_size;
    const float* x       = (const float*)d_in[0];
    const float* ln_w    = (const float*)d_in[1];
    const float* ln_b    = (const float*)d_in[2];
    const float* W_in    = (const float*)d_in[3];
    const float* W_dt    = (const float*)d_in[4];
    const float* conv_w  = (const float*)d_in[5];
    const float* conv_b  = (const float*)d_in[6];
    const float* A_log   = (const float*)d_in[7];
    const float* Dskip   = (const float*)d_in[8];
    const float* dt_bias = (const float*)d_in[9];
    const float* norm_w  = (const float*)d_in[10];
    const float* W_res   = (const float*)d_in[11];
    const float* W_out   = (const float*)d_in[12];
    float* out = (float*)d_out;

    float *dtc, *ucb, *yb, *resb;
    __half *hp, *hxn, *hx, *hg, *hwin, *hwres, *hwout;
    cudaGetSymbolAddress((void**)&hp,    g_hP);
    cudaGetSymbolAddress((void**)&dtc,   g_dt);
    cudaGetSymbolAddress((void**)&ucb,   g_uc);
    cudaGetSymbolAddress((void**)&yb,    g_y);
    cudaGetSymbolAddress((void**)&resb,  g_res);
    cudaGetSymbolAddress((void**)&hxn,   g_hXn);
    cudaGetSymbolAddress((void**)&hx,    g_hX);
    cudaGetSymbolAddress((void**)&hg,    g_hG);
    cudaGetSymbolAddress((void**)&hwin,  g_hWin);
    cudaGetSymbolAddress((void**)&hwres, g_hWres);
    cudaGetSymbolAddress((void**)&hwout, g_hWout);

    const int SMEMSZ = 3 * 32768 + 1024;
    cudaFuncSetAttribute(gemm_h<0>, cudaFuncAttributeMaxDynamicSharedMemorySize, SMEMSZ);
    cudaFuncSetAttribute(gemm_h<1>, cudaFuncAttributeMaxDynamicSharedMemorySize, SMEMSZ);

    /* fp16 conversions */
    h_cvt<<<4096, 256>>>(W_in,  hwin,  (int)((size_t)TOTOUT * DMODEL / 4));
    h_cvt<<<1024, 256>>>(W_res, hwres, DINNER * DMODEL / 4);
    h_cvt<<<1024, 256>>>(W_out, hwout, DMODEL * DINNER / 4);

    ln_kernel<<<MTOT, 256>>>(x, ln_w, ln_b, hxn, hx);

    /* p = xn @ W_in^T : 2048 x 52272, K=768  (fp16 output, M-fastest grid) */
    gemm_h<1><<<dim3(MTOT / 128, (TOTOUT + 127) / 128), 256, SMEMSZ>>>(
        hxn, hwin, hp, TOTOUT, DMODEL, DMODEL, DMODEL, TOTOUT);

    dtprep_kernel<<<MTOT / 16, 256>>>(hp, W_dt, dt_bias, conv_w, conv_b, dtc, ucb);
    scan_kernel<<<192, 64>>>(hp, dtc, ucb, A_log, Dskip, yb);

    /* res = x @ W_res^T : 2048 x 1536, K=768 */
    gemm_h<0><<<dim3(MTOT / 128, DINNER / 128), 256, SMEMSZ>>>(
        hx, hwres, resb, DINNER, DMODEL, DMODEL, DMODEL, DINNER);

    gate_kernel<<<MTOT, 256>>>(yb, hp, norm_w, resb, hg);

    /* out = g @ W_out^T : 2048 x 768, K=1536 */
    gemm_h<0><<<dim3(MTOT / 128, DMODEL / 128), 256, SMEMSZ>>>(
        hg, hwout, out, DMODEL, DINNER, DINNER, DINNER, DMODEL);
}

// round 15
// speedup vs baseline: 1.2108x; 1.1128x over previous
#include <cuda_runtime.h>
#include <cuda_fp16.h>
#include <cstdint>
#include <math.h>

#define BATCH   2
#define SEQL    1024
#define DMODEL  768
#define DINNER  1536
#define DSTATE  16
#define DTRANK  48
#define MTOT    (BATCH*SEQL)
#define TOTOUT  52272
#define OFF_U   DINNER
#define OFF_DTH (2*DINNER)
#define OFF_B   (2*DINNER + DTRANK)
#define OFF_C   (OFF_B + DINNER*DSTATE)

/* ------------------------------ scratch ------------------------------------ */
__device__ __align__(16) __half g_hP [(size_t)MTOT * TOTOUT];
__device__ float g_dt [MTOT * DINNER];
__device__ float g_uc [MTOT * DINNER];
__device__ float g_y  [MTOT * DINNER];
__device__ float g_res[MTOT * DINNER];
__device__ __align__(16) __half g_hXn [MTOT * DMODEL];
__device__ __align__(16) __half g_hX  [MTOT * DMODEL];
__device__ __align__(16) __half g_hG  [MTOT * DINNER];
__device__ __align__(16) __half g_hWin [(size_t)TOTOUT * DMODEL];
__device__ __align__(16) __half g_hWres[DINNER * DMODEL];
__device__ __align__(16) __half g_hWout[DMODEL * DINNER];

/* ------------------------------- helpers ----------------------------------- */
__device__ __forceinline__ float block_sum256(float v, float* sm) {
    int tid = threadIdx.x;
    #pragma unroll
    for (int o = 16; o; o >>= 1) v += __shfl_down_sync(0xffffffffu, v, o);
    if ((tid & 31) == 0) sm[tid >> 5] = v;
    __syncthreads();
    if (tid < 32) {
        float r = (tid < 8) ? sm[tid] : 0.f;
        #pragma unroll
        for (int o = 4; o; o >>= 1) r += __shfl_down_sync(0xffffffffu, r, o);
        if (tid == 0) sm[0] = r;
    }
    __syncthreads();
    float r = sm[0];
    __syncthreads();
    return r;
}

__global__ void h_cvt(const float* __restrict__ src, __half* __restrict__ dst, int n4) {
    int i = blockIdx.x * blockDim.x + threadIdx.x, st = gridDim.x * blockDim.x;
    for (; i < n4; i += st) {
        float4 v = ((const float4*)src)[i];
        ((__half2*)dst)[2 * i]     = __floats2half2_rn(v.x, v.y);
        ((__half2*)dst)[2 * i + 1] = __floats2half2_rn(v.z, v.w);
    }
}

/* layernorm -> hxn, plus raw x -> hx (saves a separate conversion pass) */
__global__ void ln_kernel(const float* __restrict__ x, const float* __restrict__ w,
                          const float* __restrict__ bb,
                          __half* __restrict__ out, __half* __restrict__ outx) {
    __shared__ float sm[8];
    int m = blockIdx.x, tid = threadIdx.x;
    const float* row = x + (size_t)m * DMODEL;
    float v0 = row[tid], v1 = row[tid + 256], v2 = row[tid + 512];
    float s = block_sum256(v0 + v1 + v2, sm);
    float mu = s * (1.f / (float)DMODEL);
    float d0 = v0 - mu, d1 = v1 - mu, d2 = v2 - mu;
    float q = block_sum256(d0 * d0 + d1 * d1 + d2 * d2, sm);
    float inv = rsqrtf(q * (1.f / (float)DMODEL) + 1e-5f);
    __half* o  = out  + (size_t)m * DMODEL;
    __half* ox = outx + (size_t)m * DMODEL;
    o[tid]       = __float2half_rn(d0 * inv * w[tid]       + bb[tid]);
    o[tid + 256] = __float2half_rn(d1 * inv * w[tid + 256] + bb[tid + 256]);
    o[tid + 512] = __float2half_rn(d2 * inv * w[tid + 512] + bb[tid + 512]);
    ox[tid]       = __float2half_rn(v0);
    ox[tid + 256] = __float2half_rn(v1);
    ox[tid + 512] = __float2half_rn(v2);
}

/* ============== fp16 tensor-core GEMM: C[M,N]=A[M,K]*B[N,K]^T ===============
   tile 128x128, BK=64, 3-stage cp.async, one sync/step, 2 CTAs/SM,
   M-fastest grid for L2 weight reuse. */
template<int HOUT>
__global__ void __launch_bounds__(256, 2)
gemm_h(const __half* __restrict__ A, const __half* __restrict__ B,
       void* __restrict__ Cv, int N, int K, int lda, int ldb, int ldc)
{
    extern __shared__ char smem_raw[];
    const unsigned sraw  = (unsigned)__cvta_generic_to_shared(smem_raw);
    const unsigned sbase = (sraw + 1023u) & ~1023u;
    constexpr unsigned STG = 32768u;

    const int tid = threadIdx.x, lane = tid & 31, warp = tid >> 5;
    const int wm = (warp & 1) * 64, wn = (warp >> 1) * 32;
    const int bm0 = blockIdx.x * 128, bn0 = blockIdx.y * 128;

    float acc[4][4][4];
    #pragma unroll
    for (int i = 0; i < 4; i++)
        #pragma unroll
        for (int j = 0; j < 4; j++)
            #pragma unroll
            for (int k = 0; k < 4; k++) acc[i][j][k] = 0.f;

    const int arow  = lane & 15;
    const int abyte = (lane & 16) ? 16 : 0;
    const int brow  = (lane & 7) + ((lane & 16) ? 8 : 0);
    const int bbyte = (lane & 8) ? 16 : 0;

    auto load_stage = [&](int t) {
        unsigned stg = sbase + (unsigned)(t % 3) * STG;
        int k0 = t * 64;
        #pragma unroll
        for (int i = 0; i < 4; i++) {
            int si = tid * 4 + i;
            int r = si >> 3, sg = si & 7;
            unsigned off = (unsigned)(r * 128 + sg * 16);
            unsigned sw = off ^ ((off >> 3) & 0x70u);
            const __half* g = A + (size_t)(bm0 + r) * lda + k0 + sg * 8;
            asm volatile("cp.async.cg.shared.global [%0], [%1], 16;"
                         :: "r"(stg + sw), "l"(g));
        }
        #pragma unroll
        for (int i = 0; i < 4; i++) {
            int si = tid * 4 + i;
            int r = si >> 3, sg = si & 7;
            int n = bn0 + r;
            unsigned off = (unsigned)(r * 128 + sg * 16);
            unsigned sw = off ^ ((off >> 3) & 0x70u);
            const __half* g = B + (size_t)(n < N ? n : N - 1) * ldb + k0 + sg * 8;
            int bytes = (n < N) ? 16 : 0;
            asm volatile("cp.async.cg.shared.global [%0], [%1], 16, %2;"
                         :: "r"(stg + 16384u + sw), "l"(g), "r"(bytes));
        }
    };

    auto compute_stage = [&](int s) {
        unsigned aB = sbase + (unsigned)(s % 3) * STG;
        unsigned bB = aB + 16384u;
        #pragma unroll
        for (int ks = 0; ks < 4; ks++) {
            unsigned a[4][4], b[2][4];
            #pragma unroll
            for (int mi = 0; mi < 4; mi++) {
                unsigned off = (unsigned)((wm + mi * 16 + arow) * 128 + ks * 32 + abyte);
                unsigned ad = aB + (off ^ ((off >> 3) & 0x70u));
                asm volatile("ldmatrix.sync.aligned.m8n8.x4.shared.b16 {%0,%1,%2,%3}, [%4];"
                             : "=r"(a[mi][0]), "=r"(a[mi][1]), "=r"(a[mi][2]), "=r"(a[mi][3])
                             : "r"(ad));
            }
            #pragma unroll
            for (int bg = 0; bg < 2; bg++) {
                unsigned off = (unsigned)((wn + bg * 16 + brow) * 128 + ks * 32 + bbyte);
                unsigned ad = bB + (off ^ ((off >> 3) & 0x70u));
                asm volatile("ldmatrix.sync.aligned.m8n8.x4.shared.b16 {%0,%1,%2,%3}, [%4];"
                             : "=r"(b[bg][0]), "=r"(b[bg][1]), "=r"(b[bg][2]), "=r"(b[bg][3])
                             : "r"(ad));
            }
            #pragma unroll
            for (int mi = 0; mi < 4; mi++)
                #pragma unroll
                for (int nj = 0; nj < 4; nj++) {
                    unsigned b0 = b[nj >> 1][(nj & 1) * 2];
                    unsigned b1 = b[nj >> 1][(nj & 1) * 2 + 1];
                    asm volatile(
                        "mma.sync.aligned.m16n8k16.row.col.f32.f16.f16.f32 "
                        "{%0,%1,%2,%3}, {%4,%5,%6,%7}, {%8,%9}, {%0,%1,%2,%3};"
                        : "+f"(acc[mi][nj][0]), "+f"(acc[mi][nj][1]),
                          "+f"(acc[mi][nj][2]), "+f"(acc[mi][nj][3])
                        : "r"(a[mi][0]), "r"(a[mi][1]), "r"(a[mi][2]), "r"(a[mi][3]),
                          "r"(b0), "r"(b1));
                }
        }
    };

    const int nst = K >> 6;
    load_stage(0); asm volatile("cp.async.commit_group;");
    load_stage(1); asm volatile("cp.async.commit_group;");
    for (int s = 0; s < nst; s++) {
        if (s + 1 < nst) asm volatile("cp.async.wait_group 1;");
        else             asm volatile("cp.async.wait_group 0;");
        __syncthreads();
        if (s + 2 < nst) { load_stage(s + 2); asm volatile("cp.async.commit_group;"); }
        compute_stage(s);
    }

    #pragma unroll
    for (int mi = 0; mi < 4; mi++)
        #pragma unroll
        for (int nj = 0; nj < 4; nj++) {
            int row = bm0 + wm + mi * 16 + (lane >> 2);
            int col = bn0 + wn + nj * 8 + (lane & 3) * 2;
            if (col < N) {
                if (HOUT) {
                    __half* Ch = (__half*)Cv;
                    *(__half2*)(Ch + (size_t)row * ldc + col) =
                        __floats2half2_rn(acc[mi][nj][0], acc[mi][nj][1]);
                    *(__half2*)(Ch + (size_t)(row + 8) * ldc + col) =
                        __floats2half2_rn(acc[mi][nj][2], acc[mi][nj][3]);
                } else {
                    float* C = (float*)Cv;
                    *(float2*)(C + (size_t)row * ldc + col) =
                        make_float2(acc[mi][nj][0], acc[mi][nj][1]);
                    *(float2*)(C + (size_t)(row + 8) * ldc + col) =
                        make_float2(acc[mi][nj][2], acc[mi][nj][3]);
                }
            }
        }
}

/* -------- fused dt projection + softplus/clip + causal depthwise conv ------ */
__global__ void dtprep_kernel(const __half* __restrict__ p, const float* __restrict__ Wdt,
                              const float* __restrict__ dt_bias,
                              const float* __restrict__ conv_w, const float* __restrict__ conv_b,
                              float* __restrict__ dt_out, float* __restrict__ uc_out)
{
    __shared__ float sA[16][48];
    int m0 = blockIdx.x * 16, tid = threadIdx.x;
    int l0 = m0 & (SEQL - 1);
    for (int i = tid; i < 16 * 48; i += 256)
        sA[i / 48][i % 48] = __half2float(p[(size_t)(m0 + i / 48) * TOTOUT + OFF_DTH + (i % 48)]);
    __syncthreads();
    for (int d = tid; d < DINNER; d += 256) {
        float w[48];
        #pragma unroll
        for (int k = 0; k < 48; k++) w[k] = Wdt[d * 48 + k];
        float bias = dt_bias[d];
        float4 cw = *(const float4*)(conv_w + d * 4);
        float cb = conv_b[d];
        float uu[19];
        #pragma unroll
        for (int j = 0; j < 19; j++) {
            bool valid = (l0 + j - 3) >= 0;
            uu[j] = valid ? __half2float(p[(size_t)(m0 + j - 3) * TOTOUT + OFF_U + d]) : 0.f;
        }
        #pragma unroll
        for (int r = 0; r < 16; r++) {
            float acc = bias;
            #pragma unroll
            for (int k = 0; k < 48; k++) acc = fmaf(sA[r][k], w[k], acc);
            float sp = (acc > 20.f) ? acc : log1pf(expf(acc));
            dt_out[(size_t)(m0 + r) * DINNER + d] = fminf(fmaxf(sp, 1e-4f), 1.0f);
            uc_out[(size_t)(m0 + r) * DINNER + d] =
                cb + cw.x*uu[r] + cw.y*uu[r+1] + cw.z*uu[r+2] + cw.w*uu[r+3];
        }
    }
}

/* ------- selective scan: 4 lanes/chain, depth-16 prefetch, 192 x 64thr ----- */
__global__ void scan_kernel(const __half* __restrict__ p, const float* __restrict__ dt,
                            const float* __restrict__ uc, const float* __restrict__ A_log,
                            const float* __restrict__ Dskip, float* __restrict__ y)
{
    int t = blockIdx.x * blockDim.x + threadIdx.x;   /* 12288 = 3072 chains * 4 */
    int chain = t >> 2, part = t & 3;
    int b = chain / DINNER, d = chain - b * DINNER, n0 = part * 4;

    float a0 = -__expf(A_log[d*DSTATE+n0+0]), a1 = -__expf(A_log[d*DSTATE+n0+1]);
    float a2 = -__expf(A_log[d*DSTATE+n0+2]), a3 = -__expf(A_log[d*DSTATE+n0+3]);
    float dsk = Dskip[d];
    size_t basep = (size_t)b * SEQL * TOTOUT;
    const __half* pB = p + basep + OFF_B + d * DSTATE + n0;
    const __half* pC = p + basep + OFF_C + d * DSTATE + n0;
    size_t base2 = (size_t)b * SEQL * DINNER + d;
    const float* pdt = dt + base2;
    const float* puc = uc + base2;
    float* py = y + base2;

    uint2 Bb[16], Cb[16]; float dtb[16], ucb[16];
    #pragma unroll
    for (int s = 0; s < 16; s++) {
        Bb[s]  = *(const uint2*)(pB + (size_t)s * TOTOUT);
        Cb[s]  = *(const uint2*)(pC + (size_t)s * TOTOUT);
        dtb[s] = pdt[(size_t)s * DINNER];
        ucb[s] = puc[(size_t)s * DINNER];
    }
    float h0 = 0.f, h1 = 0.f, h2 = 0.f, h3 = 0.f;
    #pragma unroll 16
    for (int l = 0; l < SEQL; l++) {
        int sl = l & 15;
        float dtv = dtb[sl], ucv = ucb[sl];
        uint2 Bu = Bb[sl], Cu = Cb[sl];
        int lp = l + 16;
        if (lp < SEQL) {
            Bb[sl]  = *(const uint2*)(pB + (size_t)lp * TOTOUT);
            Cb[sl]  = *(const uint2*)(pC + (size_t)lp * TOTOUT);
            dtb[sl] = pdt[(size_t)lp * DINNER];
            ucb[sl] = puc[(size_t)lp * DINNER];
        }
        float2 B01 = __half22float2(*(__half2*)&Bu.x);
        float2 B23 = __half22float2(*(__half2*)&Bu.y);
        float2 C01 = __half22float2(*(__half2*)&Cu.x);
        float2 C23 = __half22float2(*(__half2*)&Cu.y);
        float dtu = dtv * ucv;
        h0 = fmaf(h0, __expf(dtv*a0), dtu*B01.x);
        h1 = fmaf(h1, __expf(dtv*a1), dtu*B01.y);
        h2 = fmaf(h2, __expf(dtv*a2), dtu*B23.x);
        h3 = fmaf(h3, __expf(dtv*a3), dtu*B23.y);
        float acc = C01.x*h0 + C01.y*h1 + C23.x*h2 + C23.y*h3;
        acc += __shfl_down_sync(0xffffffffu, acc, 2, 4);
        acc += __shfl_down_sync(0xffffffffu, acc, 1, 4);
        if (part == 0) py[(size_t)l * DINNER] = fmaf(ucv, dsk, acc);
    }
}

__global__ void gate_kernel(const float* __restrict__ y, const __half* __restrict__ p,
                            const float* __restrict__ norm_w, const float* __restrict__ res,
                            __half* __restrict__ g)
{
    __shared__ float sm[8];
    int m = blockIdx.x, tid = threadIdx.x;
    float gv[6], ss = 0.f;
    #pragma unroll
    for (int i = 0; i < 6; i++) {
        int d = tid + i * 256;
        float z = __half2float(p[(size_t)m * TOTOUT + d]);
        float yv = y[(size_t)m * DINNER + d];
        gv[i] = yv * z / (1.f + __expf(-z));
        ss += gv[i] * gv[i];
    }
    float tot = block_sum256(ss, sm);
    float r = rsqrtf(tot * (1.f / (float)DINNER) + 1e-6f);
    #pragma unroll
    for (int i = 0; i < 6; i++) {
        int d = tid + i * 256;
        g[(size_t)m * DINNER + d] =
            __float2half_rn(gv[i] * r * norm_w[d] + res[(size_t)m * DINNER + d]);
    }
}

/* --------------------------------- launch ---------------------------------- */
extern "C" void kernel_launch(void* const* d_in, const int* in_sizes, int n_in,
                              void* d_out, int out_size)
{
    (void)in_sizes; (void)n_in; (void)out_size;
    const float* x       = (const float*)d_in[0];
    const float* ln_w    = (const float*)d_in[1];
    const float* ln_b    = (const float*)d_in[2];
    const float* W_in    = (const float*)d_in[3];
    const float* W_dt    = (const float*)d_in[4];
    const float* conv_w  = (const float*)d_in[5];
    const float* conv_b  = (const float*)d_in[6];
    const float* A_log   = (const float*)d_in[7];
    const float* Dskip   = (const float*)d_in[8];
    const float* dt_bias = (const float*)d_in[9];
    const float* norm_w  = (const float*)d_in[10];
    const float* W_res   = (const float*)d_in[11];
    const float* W_out   = (const float*)d_in[12];
    float* out = (float*)d_out;

    float *dtc, *ucb, *yb, *resb;
    __half *hp, *hxn, *hx, *hg, *hwin, *hwres, *hwout;
    cudaGetSymbolAddress((void**)&hp,    g_hP);
    cudaGetSymbolAddress((void**)&dtc,   g_dt);
    cudaGetSymbolAddress((void**)&ucb,   g_uc);
    cudaGetSymbolAddress((void**)&yb,    g_y);
    cudaGetSymbolAddress((void**)&resb,  g_res);
    cudaGetSymbolAddress((void**)&hxn,   g_hXn);
    cudaGetSymbolAddress((void**)&hx,    g_hX);
    cudaGetSymbolAddress((void**)&hg,    g_hG);
    cudaGetSymbolAddress((void**)&hwin,  g_hWin);
    cudaGetSymbolAddress((void**)&hwres, g_hWres);
    cudaGetSymbolAddress((void**)&hwout, g_hWout);

    const int SMEMSZ = 3 * 32768 + 1024;
    cudaFuncSetAttribute(gemm_h<0>, cudaFuncAttributeMaxDynamicSharedMemorySize, SMEMSZ);
    cudaFuncSetAttribute(gemm_h<1>, cudaFuncAttributeMaxDynamicSharedMemorySize, SMEMSZ);

    /* fp16 conversions */
    h_cvt<<<4096, 256>>>(W_in,  hwin,  (int)((size_t)TOTOUT * DMODEL / 4));
    h_cvt<<<1024, 256>>>(W_res, hwres, DINNER * DMODEL / 4);
    h_cvt<<<1024, 256>>>(W_out, hwout, DMODEL * DINNER / 4);

    ln_kernel<<<MTOT, 256>>>(x, ln_w, ln_b, hxn, hx);

    /* p = xn @ W_in^T : 2048 x 52272, K=768  (fp16 output, M-fastest grid) */
    gemm_h<1><<<dim3(MTOT / 128, (TOTOUT + 127) / 128), 256, SMEMSZ>>>(
        hxn, hwin, hp, TOTOUT, DMODEL, DMODEL, DMODEL, TOTOUT);

    dtprep_kernel<<<MTOT / 16, 256>>>(hp, W_dt, dt_bias, conv_w, conv_b, dtc, ucb);
    scan_kernel<<<192, 64>>>(hp, dtc, ucb, A_log, Dskip, yb);

    /* res = x @ W_res^T : 2048 x 1536, K=768 */
    gemm_h<0><<<dim3(MTOT / 128, DINNER / 128), 256, SMEMSZ>>>(
        hx, hwres, resb, DINNER, DMODEL, DMODEL, DMODEL, DINNER);

    gate_kernel<<<MTOT, 256>>>(yb, hp, norm_w, resb, hg);

    /* out = g @ W_out^T : 2048 x 768, K=1536 */
    gemm_h<0><<<dim3(MTOT / 128, DMODEL / 128), 256, SMEMSZ>>>(
        hg, hwout, out, DMODEL, DINNER, DINNER, DINNER, DMODEL);
}